// round 16
// baseline (speedup 1.0000x reference)
#include <cuda_runtime.h>
#include <cuda_fp16.h>
#include <cstdint>
#include <cstddef>

namespace {
constexpr int kT = 8192, kD = 2048, kF = 4096, kE = 8;
constexpr int TMm = 128;
constexpr int TN  = 128;
constexpr int ROWT = kT / TMm + kE;      // 72
constexpr int TPAD = ROWT * TMm;
constexpr int BK = 64;
constexpr int ST = 3;
constexpr int A_BYTES = TMm * BK * 2;    // 16 KB
constexpr int B_BYTES = TN * BK * 2;     // 16 KB
constexpr int STG = A_BYTES + B_BYTES;   // 32 KB
constexpr int SMEM_BYTES = ST * STG;     // 96 KB -> 2 CTAs/SM
constexpr int NTH = 128;                 // 4 warps, warp tile 64x64

constexpr long long W1_N8 = ((long long)kE * kF * kD) / 8;
constexpr long long W2_N8 = ((long long)kE * kD * kF) / 8;

// fused schedule: [xperm] then [w2cvt || GEMM1] then GEMM2
constexpr int XT1 = kF / TN;             // 32
constexpr int XT2 = kD / TN;             // 16
constexpr int NT1 = XT1 * ROWT;          // 2304
constexpr int NT2 = XT2 * ROWT;          // 1152
constexpr int NW2 = kE * XT2;            // 128 w2 panel units
constexpr int NCVT = 512;                // w2-cvt slices: 4 per panel
constexpr int SL_PER_PANEL = NCVT / NW2; // 4
constexpr int XP = ROWT;                 // 72 xperm units (ids 0..71)
constexpr int MIX = 3 * NCVT;            // 1536
constexpr int G1END = XP + NT1 + NCVT;   // 2888
constexpr int TOTAL = G1END + NT2;       // 4040
constexpr int CVT_CHUNK = (int)(W2_N8 / NCVT);   // 16384 uint4 per slice
}

__device__ int g_cursor[kE];
__device__ int g_rowtoken[TPAD];
__device__ int g_tile_expert[ROWT];
__device__ int g_xrdy[ROWT];             // xperm unit done flags
__device__ int g_w2rdy[NW2];             // per-panel slice counters (4 => ready)
__device__ int g_done1[ROWT];
__device__ __half g_xperm[(size_t)TPAD * kD];
__device__ __half g_w1h[(size_t)kE * kF * kD];
__device__ __half g_w2h[(size_t)kE * kD * kF];
__device__ __half g_h1h[(size_t)TPAD * kF];   // also: first 32KB = route temp (pre-GEMM1)

__device__ __forceinline__ uint32_t smem_u32(const void* p) {
    uint32_t a;
    asm("{ .reg .u64 t; cvta.to.shared.u64 t, %1; cvt.u32.u64 %0, t; }" : "=r"(a) : "l"(p));
    return a;
}
__device__ __forceinline__ void ldsm_x4(uint32_t* r, uint32_t addr) {
    asm volatile("ldmatrix.sync.aligned.m8n8.x4.shared.b16 {%0,%1,%2,%3}, [%4];"
                 : "=r"(r[0]), "=r"(r[1]), "=r"(r[2]), "=r"(r[3]) : "r"(addr));
}
__device__ __forceinline__ void mma_f16(float* c, const uint32_t* a, uint32_t b0, uint32_t b1) {
    asm volatile(
        "mma.sync.aligned.m16n8k16.row.col.f32.f16.f16.f32 "
        "{%0,%1,%2,%3}, {%4,%5,%6,%7}, {%8,%9}, {%0,%1,%2,%3};\n"
        : "+f"(c[0]), "+f"(c[1]), "+f"(c[2]), "+f"(c[3])
        : "r"(a[0]), "r"(a[1]), "r"(a[2]), "r"(a[3]), "r"(b0), "r"(b1));
}
__device__ __forceinline__ void cp_async16(uint32_t dst, const void* src) {
    asm volatile("cp.async.cg.shared.global [%0], [%1], 16;" :: "r"(dst), "l"(src));
}
__device__ __forceinline__ void cvt8(const float4* __restrict__ s, uint4* __restrict__ d) {
    float4 a = s[0], b = s[1];
    __half2 h0 = __floats2half2_rn(a.x, a.y), h1 = __floats2half2_rn(a.z, a.w);
    __half2 h2 = __floats2half2_rn(b.x, b.y), h3 = __floats2half2_rn(b.z, b.w);
    uint4 o;
    o.x = *(uint32_t*)&h0; o.y = *(uint32_t*)&h1;
    o.z = *(uint32_t*)&h2; o.w = *(uint32_t*)&h3;
    *d = o;
}
__device__ __forceinline__ int ld_acquire(const int* p) {
    int v;
    asm volatile("ld.acquire.gpu.global.b32 %0, [%1];" : "=r"(v) : "l"(p) : "memory");
    return v;
}
__device__ __forceinline__ float fast_silu(float v) {
    return __fdividef(v, 1.f + __expf(-v));
}

// ---------------- launch #1: w1 fp32->fp16 + token routing fused -----------
__global__ void k_prep1(const float4* __restrict__ w1, const float* __restrict__ logits) {
    long long i = (long long)blockIdx.x * blockDim.x + threadIdx.x;
    if (i < kT) {
        const float* l = logits + (size_t)i * kE;
        int best = 0; float bv = l[0];
#pragma unroll
        for (int e = 1; e < kE; e++) { float v = l[e]; if (v > bv) { bv = v; best = e; } }
        ((int*)g_h1h)[i] = best;               // temp; h1h rewritten later by GEMM1
    }
    if (i < W1_N8) cvt8(w1 + 2 * (size_t)i, ((uint4*)g_w1h) + i);
}
// ---------------- launch #2: offsets + init flags ---------------------------
__global__ void k_offsets() {
    __shared__ int sc[kE];
    if (threadIdx.x < kE) sc[threadIdx.x] = 0;
    __syncthreads();
    for (int t = threadIdx.x; t < kT; t += blockDim.x)
        atomicAdd(&sc[((int*)g_h1h)[t]], 1);
    __syncthreads();
    if (threadIdx.x == 0) {
        int off = 0;
        for (int e = 0; e < kE; e++) {
            g_cursor[e] = off;
            int nt = (sc[e] + TMm - 1) / TMm;
            for (int i = 0; i < nt; i++) g_tile_expert[off / TMm + i] = e;
            off += nt * TMm;
        }
        for (int rt = off / TMm; rt < ROWT; rt++) g_tile_expert[rt] = -1;
    }
    for (int i = threadIdx.x; i < TPAD; i += blockDim.x) g_rowtoken[i] = -1;
    for (int i = threadIdx.x; i < ROWT; i += blockDim.x) { g_done1[i] = 0; g_xrdy[i] = 0; }
    for (int i = threadIdx.x; i < NW2; i += blockDim.x) g_w2rdy[i] = 0;
}
// ---------------- launch #3: scatter ---------------------------------------
__global__ void k_scatter() {
    int t = blockIdx.x * blockDim.x + threadIdx.x;
    if (t >= kT) return;
    int e = ((int*)g_h1h)[t];
    int pos = atomicAdd(&g_cursor[e], 1);
    g_rowtoken[pos] = t;
}

// ---------------- GEMM tile body (proven R12/R15 mainloop) -----------------
template <bool FIRST>
__device__ __forceinline__ void gemm_tile(int rt, int e, int xblk, uint32_t sb,
                                          float* __restrict__ out)
{
    constexpr int K = FIRST ? kD : kF;
    constexpr int NC = K / BK;
    const int rowbase = rt * TMm;
    const int colbase = xblk * TN;

    const int tid = threadIdx.x;
    const int warp = tid >> 5, lane = tid & 31;
    const int wm = warp & 1, wn = warp >> 1;

    const __half* Abase = FIRST ? g_xperm : g_h1h;
    const __half* Wb = (FIRST ? g_w1h : g_w2h) + (size_t)e * ((size_t)(FIRST ? kF : kD) * K);

    const int q = tid & 7, r = tid >> 3;
    const __half* aptr = Abase + (size_t)(rowbase + r) * K + q * 8;
    const __half* bptr = Wb + (size_t)(colbase + r) * K + q * 8;
    const uint32_t dA = (uint32_t)(r * 128 + ((q ^ (r & 7)) << 4));

    auto prefetch = [&](int c) {
        const uint32_t base = sb + (uint32_t)((c % ST) * STG);
        const __half* ap = aptr + c * BK;
#pragma unroll
        for (int p = 0; p < 8; p++)
            cp_async16(base + dA + (uint32_t)(p * 16 * 128), ap + (size_t)p * 16 * K);
        const __half* bp = bptr + c * BK;
#pragma unroll
        for (int p = 0; p < 8; p++)
            cp_async16(base + A_BYTES + dA + (uint32_t)(p * 16 * 128), bp + (size_t)p * 16 * K);
        asm volatile("cp.async.commit_group;" ::: "memory");
    };

    prefetch(0);
    prefetch(1);

    const int rowA = wm * 64 + (lane & 15);
    const int kgA = lane >> 4;
    const int rowB = wn * 64 + ((lane >> 4) << 3) + (lane & 7);
    const int kgB = (lane >> 3) & 1;

    float acc[4][8][4];
#pragma unroll
    for (int i = 0; i < 4; i++)
#pragma unroll
        for (int j = 0; j < 8; j++)
#pragma unroll
            for (int v = 0; v < 4; v++) acc[i][j][v] = 0.f;

#pragma unroll 1
    for (int c = 0; c < NC; c++) {
        if (c < NC - 1) asm volatile("cp.async.wait_group 1;" ::: "memory");
        else            asm volatile("cp.async.wait_group 0;" ::: "memory");
        __syncthreads();
        if (c + 2 < NC) prefetch(c + 2);

        const uint32_t stA = sb + (uint32_t)((c % ST) * STG);
        const uint32_t stB = stA + A_BYTES;
#pragma unroll
        for (int s = 0; s < 4; s++) {
            uint32_t a[4][4];
#pragma unroll
            for (int mi = 0; mi < 4; mi++) {
                const int rr = rowA + mi * 16;
                ldsm_x4(a[mi], stA + (uint32_t)(rr * 128 + (((2 * s + kgA) ^ (rr & 7)) << 4)));
            }
            uint32_t b[4][4];
#pragma unroll
            for (int nj2 = 0; nj2 < 4; nj2++) {
                const int rr = rowB + nj2 * 16;
                ldsm_x4(b[nj2], stB + (uint32_t)(rr * 128 + (((2 * s + kgB) ^ (rr & 7)) << 4)));
            }
#pragma unroll
            for (int mi = 0; mi < 4; mi++)
#pragma unroll
                for (int nj = 0; nj < 8; nj++)
                    mma_f16(acc[mi][nj], a[mi], b[nj >> 1][(nj & 1) * 2], b[nj >> 1][(nj & 1) * 2 + 1]);
        }
    }

    const int g = lane >> 2, tig = lane & 3;
#pragma unroll
    for (int mi = 0; mi < 4; mi++) {
#pragma unroll
        for (int rr = 0; rr < 2; rr++) {
            const int lrow = rowbase + wm * 64 + mi * 16 + g + rr * 8;
            if (FIRST) {
                __half* hp = g_h1h + (size_t)lrow * kF + colbase;
#pragma unroll
                for (int nj = 0; nj < 8; nj++) {
                    const int col = wn * 64 + nj * 8 + tig * 2;
                    __half2 h = __floats2half2_rn(fast_silu(acc[mi][nj][rr * 2 + 0]),
                                                  fast_silu(acc[mi][nj][rr * 2 + 1]));
                    *(uint32_t*)(hp + col) = *(uint32_t*)&h;
                }
            } else {
                const int tok = g_rowtoken[lrow];
                if (tok >= 0) {
                    float* op = out + (size_t)tok * kD + colbase;
#pragma unroll
                    for (int nj = 0; nj < 8; nj++) {
                        const int col = wn * 64 + nj * 8 + tig * 2;
                        float2 st;
                        st.x = acc[mi][nj][rr * 2 + 0];
                        st.y = acc[mi][nj][rr * 2 + 1];
                        *(float2*)(op + col) = st;
                    }
                }
            }
        }
    }
}

// ---------------- launch #4: fused [xperm] [w2cvt || GEMM1] GEMM2 ----------
// ids: [0,72):    xperm unit rt (token gather + cvt + zero-pad) -> g_xrdy[rt]
//      [72,1608): o%3==2 -> w2 cvt slice o/3 (panel = slice/4); else GEMM1
//      [1608,2888): GEMM1 tile (spins on g_xrdy[rt])
//      [2888,4040): GEMM2 tile (spins on its w2 panel + done1[rt]==32)
__global__ __launch_bounds__(NTH, 2) void k_moe(const float4* __restrict__ w2src,
                                                const float4* __restrict__ hs,
                                                float* __restrict__ out)
{
    extern __shared__ char smem[];
    const uint32_t sb = smem_u32(smem);
    const int tid = threadIdx.x;
    const int id = blockIdx.x;

    if (id < XP) {
        // ---- xperm unit: gather+convert+zero-pad rows rt*128..+127 ----
        const int rt = id;
#pragma unroll 4
        for (int i = tid; i < 128 * 256; i += NTH) {
            const int row = rt * 128 + (i >> 8);
            const int q = i & 255;
            const int tok = g_rowtoken[row];
            uint4 o = make_uint4(0, 0, 0, 0);
            if (tok >= 0) cvt8(hs + (size_t)tok * (kD / 4) + 2 * q, &o);
            ((uint4*)g_xperm)[(size_t)row * 256 + q] = o;
        }
        __threadfence();
        __syncthreads();
        if (tid == 0) atomicExch(&g_xrdy[rt], 1);
        return;
    }
    const int o = id - XP;
    if (id < G1END) {
        if (o < MIX && (o % 3) == 2) {
            // ---- w2 fp32->fp16 slice (1/4 panel) ----
            const int slice = o / 3;
            const long long base = (long long)slice * CVT_CHUNK;
            uint4* dst = (uint4*)g_w2h;
#pragma unroll 4
            for (int i = tid; i < CVT_CHUNK; i += NTH)
                cvt8(w2src + 2 * (size_t)(base + i), dst + base + i);
            __threadfence();
            __syncthreads();
            if (tid == 0) atomicAdd(&g_w2rdy[slice / SL_PER_PANEL], 1);
            return;
        }
        const int g1 = (o < MIX) ? (o - (o + 1) / 3) : (o - NCVT);
        const int rt = g1 >> 5, xblk = g1 & 31;
        const int e = g_tile_expert[rt];
        if (e >= 0) {
            if (tid == 0)
                while (!ld_acquire(&g_xrdy[rt])) __nanosleep(128);
            __syncthreads();
            gemm_tile<true>(rt, e, xblk, sb, out);
        }
        __threadfence();
        __syncthreads();
        if (tid == 0) atomicAdd(&g_done1[rt], 1);
    } else {
        const int g2 = id - G1END;
        const int rt = g2 >> 4, xblk = g2 & 15;
        const int e = g_tile_expert[rt];
        if (e < 0) return;
        if (tid == 0) {
            while (ld_acquire(&g_w2rdy[e * XT2 + xblk]) < SL_PER_PANEL) __nanosleep(128);
            while (ld_acquire(&g_done1[rt]) < XT1) __nanosleep(128);
        }
        __syncthreads();
        gemm_tile<false>(rt, e, xblk, sb, out);
    }
}

// ---------------- entry ----------------
extern "C" void kernel_launch(void* const* d_in, const int* in_sizes, int n_in,
                              void* d_out, int out_size) {
    const float* hs     = (const float*)d_in[0];
    const float* logits = (const float*)d_in[1];
    const float* w1     = (const float*)d_in[2];
    const float* w2     = (const float*)d_in[3];
    float* out = (float*)d_out;

    cudaFuncSetAttribute(k_moe, cudaFuncAttributeMaxDynamicSharedMemorySize, SMEM_BYTES);

    k_prep1<<<(unsigned)((W1_N8 + 255) / 256), 256>>>((const float4*)w1, logits);
    k_offsets<<<1, 256>>>();
    k_scatter<<<kT / 256, 256>>>();
    k_moe<<<TOTAL, NTH, SMEM_BYTES>>>((const float4*)w2, (const float4*)hs, out);
}

// round 17
// speedup vs baseline: 1.0990x; 1.0990x over previous
#include <cuda_runtime.h>
#include <cuda_fp16.h>
#include <cstdint>
#include <cstddef>

namespace {
constexpr int kT = 8192, kD = 2048, kF = 4096, kE = 8;
constexpr int TMm = 128;
constexpr int TN  = 128;
constexpr int ROWT = kT / TMm + kE;      // 72
constexpr int TPAD = ROWT * TMm;
constexpr int BK = 64;
constexpr int ST = 3;
constexpr int A_BYTES = TMm * BK * 2;    // 16 KB
constexpr int B_BYTES = TN * BK * 2;     // 16 KB
constexpr int STG = A_BYTES + B_BYTES;   // 32 KB
constexpr int SMEM_BYTES = ST * STG;     // 96 KB -> 2 CTAs/SM
constexpr int NTH = 128;                 // 4 warps, warp tile 64x64

constexpr long long W1_N8 = ((long long)kE * kF * kD) / 8;   // 8388608
constexpr long long W2_N8 = ((long long)kE * kD * kF) / 8;

// k_pre grid: 1 routing CTA + 72 xperm CTAs + 32768 w1-cvt CTAs
constexpr int XP = ROWT;                             // 72
constexpr int PRE_CVT = (int)(W1_N8 / 256);          // 32768
constexpr int PRE_TOTAL = 1 + XP + PRE_CVT;          // 32841

// k_moe schedule (R15, proven): [w2cvt || GEMM1] then GEMM2
constexpr int XT1 = kF / TN;             // 32
constexpr int XT2 = kD / TN;             // 16
constexpr int NT1 = XT1 * ROWT;          // 2304
constexpr int NT2 = XT2 * ROWT;          // 1152
constexpr int NW2 = kE * XT2;            // 128 w2 panel units
constexpr int NCVT = 512;                // w2-cvt slices: 4 per panel
constexpr int SL_PER_PANEL = NCVT / NW2; // 4
constexpr int MIX = 3 * NCVT;            // 1536
constexpr int PH1 = NT1 + NCVT;          // 2816
constexpr int TOTAL = PH1 + NT2;         // 3968
constexpr int CVT_CHUNK = (int)(W2_N8 / NCVT);   // 16384 uint4 per slice
}

__device__ int g_rowtoken[TPAD];
__device__ int g_tile_expert[ROWT];
__device__ int g_pre_done;               // set by k_pre CTA0, cleared by k_moe
__device__ int g_w2rdy[NW2];             // per-panel slice counters (4 => ready)
__device__ int g_done1[ROWT];
__device__ __half g_xperm[(size_t)TPAD * kD];
__device__ __half g_w1h[(size_t)kE * kF * kD];
__device__ __half g_w2h[(size_t)kE * kD * kF];
__device__ __half g_h1h[(size_t)TPAD * kF];

__device__ __forceinline__ uint32_t smem_u32(const void* p) {
    uint32_t a;
    asm("{ .reg .u64 t; cvta.to.shared.u64 t, %1; cvt.u32.u64 %0, t; }" : "=r"(a) : "l"(p));
    return a;
}
__device__ __forceinline__ void ldsm_x4(uint32_t* r, uint32_t addr) {
    asm volatile("ldmatrix.sync.aligned.m8n8.x4.shared.b16 {%0,%1,%2,%3}, [%4];"
                 : "=r"(r[0]), "=r"(r[1]), "=r"(r[2]), "=r"(r[3]) : "r"(addr));
}
__device__ __forceinline__ void mma_f16(float* c, const uint32_t* a, uint32_t b0, uint32_t b1) {
    asm volatile(
        "mma.sync.aligned.m16n8k16.row.col.f32.f16.f16.f32 "
        "{%0,%1,%2,%3}, {%4,%5,%6,%7}, {%8,%9}, {%0,%1,%2,%3};\n"
        : "+f"(c[0]), "+f"(c[1]), "+f"(c[2]), "+f"(c[3])
        : "r"(a[0]), "r"(a[1]), "r"(a[2]), "r"(a[3]), "r"(b0), "r"(b1));
}
__device__ __forceinline__ void cp_async16(uint32_t dst, const void* src) {
    asm volatile("cp.async.cg.shared.global [%0], [%1], 16;" :: "r"(dst), "l"(src));
}
__device__ __forceinline__ void cvt8(const float4* __restrict__ s, uint4* __restrict__ d) {
    float4 a = s[0], b = s[1];
    __half2 h0 = __floats2half2_rn(a.x, a.y), h1 = __floats2half2_rn(a.z, a.w);
    __half2 h2 = __floats2half2_rn(b.x, b.y), h3 = __floats2half2_rn(b.z, b.w);
    uint4 o;
    o.x = *(uint32_t*)&h0; o.y = *(uint32_t*)&h1;
    o.z = *(uint32_t*)&h2; o.w = *(uint32_t*)&h3;
    *d = o;
}
__device__ __forceinline__ int ld_acquire(const int* p) {
    int v;
    asm volatile("ld.acquire.gpu.global.b32 %0, [%1];" : "=r"(v) : "l"(p) : "memory");
    return v;
}
__device__ __forceinline__ float fast_silu(float v) {
    return __fdividef(v, 1.f + __expf(-v));
}

// ---------------- launch #1: routing + xperm + w1 cvt in ONE kernel --------
// bid 0      : route + offsets + scatter (smem-local), publish g_pre_done
// bid 1..72  : xperm unit rt=bid-1 (spins on g_pre_done; CTA0 is in wave 1)
// bid 73+    : w1 fp32->fp16 bulk (covers the above with DRAM-bound work)
__global__ __launch_bounds__(256) void k_pre(const float4* __restrict__ w1,
                                             const float* __restrict__ logits,
                                             const float4* __restrict__ hs)
{
    const int tid = threadIdx.x;
    const int bid = blockIdx.x;

    if (bid == 0) {
        __shared__ int sassign[kT];      // 32 KB
        __shared__ int scnt[kE];
        __shared__ int scur[kE];
        if (tid < kE) scnt[tid] = 0;
        __syncthreads();
        // route
        for (int t = tid; t < kT; t += 256) {
            const float* l = logits + (size_t)t * kE;
            int best = 0; float bv = l[0];
#pragma unroll
            for (int e = 1; e < kE; e++) { float v = l[e]; if (v > bv) { bv = v; best = e; } }
            sassign[t] = best;
            atomicAdd(&scnt[best], 1);
        }
        __syncthreads();
        // offsets + tile map
        if (tid == 0) {
            int off = 0;
            for (int e = 0; e < kE; e++) {
                scur[e] = off;
                int nt = (scnt[e] + TMm - 1) / TMm;
                for (int i = 0; i < nt; i++) g_tile_expert[off / TMm + i] = e;
                off += nt * TMm;
            }
            for (int rt = off / TMm; rt < ROWT; rt++) g_tile_expert[rt] = -1;
        }
        for (int i = tid; i < TPAD; i += 256) g_rowtoken[i] = -1;
        for (int i = tid; i < ROWT; i += 256) g_done1[i] = 0;
        for (int i = tid; i < NW2; i += 256) g_w2rdy[i] = 0;
        __syncthreads();
        // two-pass scatter (no hot global atomics)
        int c[kE];
#pragma unroll
        for (int e = 0; e < kE; e++) c[e] = 0;
        for (int t = tid; t < kT; t += 256) c[sassign[t]]++;
        int base[kE];
#pragma unroll
        for (int e = 0; e < kE; e++) base[e] = c[e] ? atomicAdd(&scur[e], c[e]) : 0;
        for (int t = tid; t < kT; t += 256) {
            int e = sassign[t];
            g_rowtoken[base[e]++] = t;
        }
        __threadfence();
        __syncthreads();
        if (tid == 0) atomicExch(&g_pre_done, 1);
        return;
    }
    if (bid <= XP) {
        // xperm unit: token gather + fp32->fp16 + zero-pad for rows rt*128..+127
        if (tid == 0) {
            while (!ld_acquire(&g_pre_done)) __nanosleep(256);
        }
        __syncthreads();
        const int rt = bid - 1;
#pragma unroll 4
        for (int i = tid; i < 128 * 256; i += 256) {
            const int row = rt * 128 + (i >> 8);
            const int q = i & 255;
            const int tok = g_rowtoken[row];
            uint4 o = make_uint4(0, 0, 0, 0);
            if (tok >= 0) cvt8(hs + (size_t)tok * (kD / 4) + 2 * q, &o);
            ((uint4*)g_xperm)[(size_t)row * 256 + q] = o;
        }
        return;
    }
    // w1 bulk conversion
    long long i = (long long)(bid - 1 - XP) * 256 + tid;
    if (i < W1_N8) cvt8(w1 + 2 * (size_t)i, ((uint4*)g_w1h) + i);
}

// ---------------- GEMM tile body (proven R12/R15 mainloop, UNchanged) ------
template <bool FIRST>
__device__ __forceinline__ void gemm_tile(int rt, int e, int xblk, uint32_t sb,
                                          float* __restrict__ out)
{
    constexpr int K = FIRST ? kD : kF;
    constexpr int NC = K / BK;
    const int rowbase = rt * TMm;
    const int colbase = xblk * TN;

    const int tid = threadIdx.x;
    const int warp = tid >> 5, lane = tid & 31;
    const int wm = warp & 1, wn = warp >> 1;

    const __half* Abase = FIRST ? g_xperm : g_h1h;
    const __half* Wb = (FIRST ? g_w1h : g_w2h) + (size_t)e * ((size_t)(FIRST ? kF : kD) * K);

    const int q = tid & 7, r = tid >> 3;
    const __half* aptr = Abase + (size_t)(rowbase + r) * K + q * 8;
    const __half* bptr = Wb + (size_t)(colbase + r) * K + q * 8;
    const uint32_t dA = (uint32_t)(r * 128 + ((q ^ (r & 7)) << 4));

    auto prefetch = [&](int c) {
        const uint32_t base = sb + (uint32_t)((c % ST) * STG);
        const __half* ap = aptr + c * BK;
#pragma unroll
        for (int p = 0; p < 8; p++)
            cp_async16(base + dA + (uint32_t)(p * 16 * 128), ap + (size_t)p * 16 * K);
        const __half* bp = bptr + c * BK;
#pragma unroll
        for (int p = 0; p < 8; p++)
            cp_async16(base + A_BYTES + dA + (uint32_t)(p * 16 * 128), bp + (size_t)p * 16 * K);
        asm volatile("cp.async.commit_group;" ::: "memory");
    };

    prefetch(0);
    prefetch(1);

    const int rowA = wm * 64 + (lane & 15);
    const int kgA = lane >> 4;
    const int rowB = wn * 64 + ((lane >> 4) << 3) + (lane & 7);
    const int kgB = (lane >> 3) & 1;

    float acc[4][8][4];
#pragma unroll
    for (int i = 0; i < 4; i++)
#pragma unroll
        for (int j = 0; j < 8; j++)
#pragma unroll
            for (int v = 0; v < 4; v++) acc[i][j][v] = 0.f;

#pragma unroll 1
    for (int c = 0; c < NC; c++) {
        if (c < NC - 1) asm volatile("cp.async.wait_group 1;" ::: "memory");
        else            asm volatile("cp.async.wait_group 0;" ::: "memory");
        __syncthreads();
        if (c + 2 < NC) prefetch(c + 2);

        const uint32_t stA = sb + (uint32_t)((c % ST) * STG);
        const uint32_t stB = stA + A_BYTES;
#pragma unroll
        for (int s = 0; s < 4; s++) {
            uint32_t a[4][4];
#pragma unroll
            for (int mi = 0; mi < 4; mi++) {
                const int rr = rowA + mi * 16;
                ldsm_x4(a[mi], stA + (uint32_t)(rr * 128 + (((2 * s + kgA) ^ (rr & 7)) << 4)));
            }
            uint32_t b[4][4];
#pragma unroll
            for (int nj2 = 0; nj2 < 4; nj2++) {
                const int rr = rowB + nj2 * 16;
                ldsm_x4(b[nj2], stB + (uint32_t)(rr * 128 + (((2 * s + kgB) ^ (rr & 7)) << 4)));
            }
#pragma unroll
            for (int mi = 0; mi < 4; mi++)
#pragma unroll
                for (int nj = 0; nj < 8; nj++)
                    mma_f16(acc[mi][nj], a[mi], b[nj >> 1][(nj & 1) * 2], b[nj >> 1][(nj & 1) * 2 + 1]);
        }
    }

    const int g = lane >> 2, tig = lane & 3;
#pragma unroll
    for (int mi = 0; mi < 4; mi++) {
#pragma unroll
        for (int rr = 0; rr < 2; rr++) {
            const int lrow = rowbase + wm * 64 + mi * 16 + g + rr * 8;
            if (FIRST) {
                __half* hp = g_h1h + (size_t)lrow * kF + colbase;
#pragma unroll
                for (int nj = 0; nj < 8; nj++) {
                    const int col = wn * 64 + nj * 8 + tig * 2;
                    __half2 h = __floats2half2_rn(fast_silu(acc[mi][nj][rr * 2 + 0]),
                                                  fast_silu(acc[mi][nj][rr * 2 + 1]));
                    *(uint32_t*)(hp + col) = *(uint32_t*)&h;
                }
            } else {
                const int tok = g_rowtoken[lrow];
                if (tok >= 0) {
                    float* op = out + (size_t)tok * kD + colbase;
#pragma unroll
                    for (int nj = 0; nj < 8; nj++) {
                        const int col = wn * 64 + nj * 8 + tig * 2;
                        float2 st;
                        st.x = acc[mi][nj][rr * 2 + 0];
                        st.y = acc[mi][nj][rr * 2 + 1];
                        *(float2*)(op + col) = st;
                    }
                }
            }
        }
    }
}

// ---------------- launch #2: fused [w2cvt || GEMM1] then GEMM2 (R15) -------
__global__ __launch_bounds__(NTH, 2) void k_moe(const float4* __restrict__ w2src,
                                                float* __restrict__ out)
{
    extern __shared__ char smem[];
    const uint32_t sb = smem_u32(smem);
    const int tid = threadIdx.x;
    const int id = blockIdx.x;

    if (id == 0 && tid == 0) g_pre_done = 0;   // reset for next graph replay

    if (id < PH1) {
        if (id < MIX && (id % 3) == 2) {
            // ---- w2 fp32->fp16 slice (1/4 of a panel) ----
            const int slice = id / 3;
            const long long base = (long long)slice * CVT_CHUNK;
            uint4* dst = (uint4*)g_w2h;
#pragma unroll 4
            for (int i = tid; i < CVT_CHUNK; i += NTH)
                cvt8(w2src + 2 * (size_t)(base + i), dst + base + i);
            __threadfence();
            __syncthreads();
            if (tid == 0) atomicAdd(&g_w2rdy[slice / SL_PER_PANEL], 1);
            return;
        }
        const int g1 = (id < MIX) ? (id - (id + 1) / 3) : (id - NCVT);
        const int rt = g1 >> 5, xblk = g1 & 31;
        const int e = g_tile_expert[rt];
        if (e >= 0) gemm_tile<true>(rt, e, xblk, sb, out);
        __threadfence();
        __syncthreads();
        if (tid == 0) atomicAdd(&g_done1[rt], 1);
    } else {
        const int g2 = id - PH1;
        const int rt = g2 >> 4, xblk = g2 & 15;
        const int e = g_tile_expert[rt];
        if (e < 0) return;
        if (tid == 0) {
            while (ld_acquire(&g_w2rdy[e * XT2 + xblk]) < SL_PER_PANEL) __nanosleep(128);
            while (ld_acquire(&g_done1[rt]) < XT1) __nanosleep(128);
        }
        __syncthreads();
        gemm_tile<false>(rt, e, xblk, sb, out);
    }
}

// ---------------- entry ----------------
extern "C" void kernel_launch(void* const* d_in, const int* in_sizes, int n_in,
                              void* d_out, int out_size) {
    const float* hs     = (const float*)d_in[0];
    const float* logits = (const float*)d_in[1];
    const float* w1     = (const float*)d_in[2];
    const float* w2     = (const float*)d_in[3];
    float* out = (float*)d_out;

    cudaFuncSetAttribute(k_moe, cudaFuncAttributeMaxDynamicSharedMemorySize, SMEM_BYTES);

    k_pre<<<PRE_TOTAL, 256>>>((const float4*)w1, logits, (const float4*)hs);
    k_moe<<<TOTAL, NTH, SMEM_BYTES>>>((const float4*)w2, out);
}